// round 8
// baseline (speedup 1.0000x reference)
#include <cuda_runtime.h>
#include <cstdint>

// ---------------- geometry ----------------
#define NB    8
#define CC    256
#define HH    52
#define WW    52
#define FNO   512
#define HP    54
#define WP    54
#define ROWS_N (HP*WP)          // 2916
#define MGLOB  (NB*ROWS_N)      // 23328
#define OHW    (HH*WW)          // 2704

// ---------------- GEMM tiling ----------------
#define BM 128
#define BN 64
#define BK 32                   // channels per stage (32 int8 bytes = 2x16B chunks)
#define STAGES 4
#define ITERS  72               // 9 taps * (256/32)
#define A_SM   (BM*BK)          // 4096 B (chunk-major: 2 chunks x 128 rows x 16B)
#define B_SM   (3*BN*BK)        // 6144 B (3 splits x [2 chunks x 64 rows x 16B])
#define STG_SM (A_SM + B_SM)    // 10240
#define SMEM_TOTAL (STAGES*STG_SM)   // 40960
#define MTILES ((MGLOB + BM - 1) / BM)   // 183

// ---------------- device scratch ----------------
__device__ int8_t g_x8[MGLOB * CC];              // ~6 MB padded NHWC quantized int8
__device__ int8_t g_w8[3 * 9 * FNO * CC];        // ~3.5 MB [split][tap][f][c] int8
__device__ float  g_s1[FNO];                     // per-f level-1 scale

// ---------------- asm helpers ----------------
__device__ __forceinline__ uint32_t smem_u32(const void* p) {
    uint32_t a;
    asm("{ .reg .u64 t; cvta.to.shared.u64 t, %1; cvt.u32.u64 %0, t; }" : "=r"(a) : "l"(p));
    return a;
}
__device__ __forceinline__ void cp16(uint32_t s, const void* g) {
    asm volatile("cp.async.cg.shared.global [%0], [%1], 16;" :: "r"(s), "l"(g));
}
__device__ __forceinline__ void ldsm4(uint32_t& r0, uint32_t& r1, uint32_t& r2, uint32_t& r3,
                                      uint32_t a) {
    asm volatile("ldmatrix.sync.aligned.m8n8.x4.shared.b16 {%0,%1,%2,%3}, [%4];"
                 : "=r"(r0), "=r"(r1), "=r"(r2), "=r"(r3) : "r"(a));
}
__device__ __forceinline__ void imma16832(int* d, const uint32_t* a, const uint32_t* b) {
    asm volatile("mma.sync.aligned.m16n8k32.row.col.s32.s8.s8.s32 "
                 "{%0,%1,%2,%3}, {%4,%5,%6,%7}, {%8,%9}, {%0,%1,%2,%3};"
                 : "+r"(d[0]), "+r"(d[1]), "+r"(d[2]), "+r"(d[3])
                 : "r"(a[0]), "r"(a[1]), "r"(a[2]), "r"(a[3]), "r"(b[0]), "r"(b[1]));
}

// ---------------- kernel 0: zero padding halo of g_x8 ----------------
__global__ void zero_halo_kernel() {
    int idx = blockIdx.x * blockDim.x + threadIdx.x;
    const int total = NB * 212 * (CC / 16);   // one uint4 (16 int8) per thread
    if (idx >= total) return;
    int v = idx & 15;
    int h = (idx >> 4) % 212;
    int n = idx / (212 * 16);
    int y, x;
    if (h < 54)       { y = 0;  x = h; }
    else if (h < 108) { y = 53; x = h - 54; }
    else { int r = h - 108; y = 1 + (r >> 1); x = (r & 1) ? 53 : 0; }
    uint4 z = {0, 0, 0, 0};
    reinterpret_cast<uint4*>(g_x8 + ((size_t)n * ROWS_N + y * WP + x) * CC)[v] = z;
}

// ---------------- kernel 1: quantize to int8 + NCHW->NHWC (interior) ---------
__global__ void quant_kernel(const float* __restrict__ in) {
    __shared__ float tile[32][33];
    const int n = blockIdx.z, y = blockIdx.y;
    const int xt = blockIdx.x & 1, ct = blockIdx.x >> 1;
    const int tx = threadIdx.x, ty = threadIdx.y;

    int x = xt * 32 + tx, c = ct * 32 + ty;
    if (x < WW) {
        float v = in[((n * CC + c) * HH + y) * WW + x];
        v = rintf(v * 20.0f);
        tile[ty][tx] = fminf(127.0f, fmaxf(-128.0f, v));
    }
    __syncthreads();
    int x2 = xt * 32 + ty, c2 = ct * 32 + tx;
    if (x2 < WW)
        g_x8[((size_t)n * ROWS_N + (y + 1) * WP + (x2 + 1)) * CC + c2] =
            (int8_t)(int)tile[tx][ty];
}

// ---------------- kernel 2a: per-f scale s1 = max|w|/127 ----------------
__global__ void s1_kernel(const float* __restrict__ w) {
    __shared__ float red[128];
    const int f = blockIdx.x;
    const int t = threadIdx.x;
    float m = 0.0f;
    for (int i = t; i < CC * 9; i += 128)
        m = fmaxf(m, fabsf(w[(size_t)i * FNO + f]));
    red[t] = m;
    __syncthreads();
    for (int s = 64; s > 0; s >>= 1) {
        if (t < s) red[t] = fmaxf(red[t], red[t + s]);
        __syncthreads();
    }
    if (t == 0) g_s1[f] = fmaxf(red[0], 1e-30f) * (1.0f / 127.0f);
}

// ---------------- kernel 2b: 3-level int8 weight quantization + transpose ----
// w = s1*(q1 + q2/128 + q3/16384) + tiny residual
__global__ void wq_kernel(const float* __restrict__ w) {
    __shared__ int8_t t0[32][33], t1[32][33], t2[32][33];
    const int tap = blockIdx.z;
    const int tx = threadIdx.x, ty = threadIdx.y;
    const int c = blockIdx.y * 32 + ty;
    const int f = blockIdx.x * 32 + tx;

    float v  = w[((size_t)c * 9 + tap) * FNO + f];
    float s1 = g_s1[f];
    float inv = 1.0f / s1;
    float q1 = rintf(v * inv);
    q1 = fminf(127.0f, fmaxf(-127.0f, q1));
    float r1 = v - s1 * q1;
    float q2 = rintf(r1 * inv * 128.0f);
    q2 = fminf(127.0f, fmaxf(-127.0f, q2));
    float r2 = r1 - q2 * s1 * 0.0078125f;
    float q3 = rintf(r2 * inv * 16384.0f);
    q3 = fminf(127.0f, fmaxf(-127.0f, q3));
    t0[ty][tx] = (int8_t)(int)q1;
    t1[ty][tx] = (int8_t)(int)q2;
    t2[ty][tx] = (int8_t)(int)q3;
    __syncthreads();

    const int c2 = blockIdx.y * 32 + tx;
    const int f2 = blockIdx.x * 32 + ty;
    size_t base = ((size_t)tap * FNO + f2) * CC + c2;
    const size_t sstr = (size_t)9 * FNO * CC;
    g_w8[base]            = t0[tx][ty];
    g_w8[base + sstr]     = t1[tx][ty];
    g_w8[base + 2 * sstr] = t2[tx][ty];
}

// ---------------- kernel 3: 3-pass int8 IMMA implicit-GEMM conv --------------
// 256 threads = 8 warps (4m x 2n), warp tile 32x32, CTA tile 128x64.
__global__ __launch_bounds__(256, 1)
void conv_mma_kernel(const float* __restrict__ bias, float* __restrict__ out) {
    extern __shared__ char smem[];
    const uint32_t sb = smem_u32(smem);
    const int tid  = threadIdx.x;
    const int lane = tid & 31, wid = tid >> 5;
    const int fbase = blockIdx.x * BN;
    const int mbase = blockIdx.y * BM;
    const int wm = (wid & 3) << 5;   // warp m-offset: 0/32/64/96
    const int wn = (wid >> 2) << 5;  // warp n-offset: 0/32

    int acc[3][2][4][4];             // [split][mi(16)][n8 group][frag]
#pragma unroll
    for (int s = 0; s < 3; ++s)
#pragma unroll
        for (int a = 0; a < 2; ++a)
#pragma unroll
            for (int b = 0; b < 4; ++b)
#pragma unroll
                for (int c = 0; c < 4; ++c) acc[s][a][b][c] = 0;

    auto issue = [&](int it) {
        const int tap = it >> 3;
        const int c0  = (it & 7) << 5;
        const int taprow = (tap / 3) * WP + (tap % 3);
        const uint32_t sA = sb + (uint32_t)(it & (STAGES - 1)) * STG_SM;
        const uint32_t sB = sA + A_SM;
        // A: 256 chunks (128 rows x 2): one per thread. chunk-major layout.
        {
            int r = tid >> 1, p = tid & 1;
            int grow = mbase + r + taprow;
            if (grow > MGLOB - 1) grow = MGLOB - 1;
            cp16(sA + p * 2048 + r * 16, g_x8 + (size_t)grow * CC + c0 + (p << 4));
        }
        // B: 384 chunks (3 splits x 64 rows x 2)
        {
            int cid = tid;           // 0..255 -> splits 0,1
            int sp = cid >> 7, rem = cid & 127;
            int fr = rem >> 1, p = rem & 1;
            cp16(sB + sp * 2048 + p * 1024 + fr * 16,
                 g_w8 + ((size_t)(sp * 9 + tap) * FNO + fbase + fr) * CC + c0 + (p << 4));
            if (tid < 128) {         // split 2
                int fr2 = tid >> 1, p2 = tid & 1;
                cp16(sB + 2 * 2048 + p2 * 1024 + fr2 * 16,
                     g_w8 + ((size_t)(2 * 9 + tap) * FNO + fbase + fr2) * CC + c0 + (p2 << 4));
            }
        }
        asm volatile("cp.async.commit_group;" ::: "memory");
    };

    issue(0); issue(1); issue(2);

#pragma unroll 1
    for (int i = 0; i < ITERS; ++i) {
        asm volatile("cp.async.wait_group %0;" :: "n"(STAGES - 2) : "memory");
        __syncthreads();

        int nx = i + STAGES - 1;
        if (nx < ITERS) issue(nx);
        else asm volatile("cp.async.commit_group;" ::: "memory");

        const uint32_t sA = sb + (uint32_t)(i & (STAGES - 1)) * STG_SM;
        const uint32_t sB = sA + A_SM;

        // A fragments: 2 x (16 rows x 32 int8)
        uint32_t a[2][4];
#pragma unroll
        for (int mi = 0; mi < 2; ++mi) {
            uint32_t addr = sA + (lane >> 4) * 2048 + (wm + (mi << 4) + (lane & 15)) * 16;
            ldsm4(a[mi][0], a[mi][1], a[mi][2], a[mi][3], addr);
        }
        // B fragments: 3 splits x 2 x (16 n-rows x 32 int8)
        uint32_t b[3][2][4];
#pragma unroll
        for (int sp = 0; sp < 3; ++sp)
#pragma unroll
            for (int nq = 0; nq < 2; ++nq) {
                uint32_t addr = sB + sp * 2048 + ((lane >> 3) & 1) * 1024
                              + (wn + (nq << 4) + ((lane >> 4) << 3) + (lane & 7)) * 16;
                ldsm4(b[sp][nq][0], b[sp][nq][1], b[sp][nq][2], b[sp][nq][3], addr);
            }
#pragma unroll
        for (int sp = 0; sp < 3; ++sp)
#pragma unroll
            for (int mi = 0; mi < 2; ++mi)
#pragma unroll
                for (int nq = 0; nq < 2; ++nq) {
                    imma16832(acc[sp][mi][nq * 2],     a[mi], b[sp][nq]);
                    imma16832(acc[sp][mi][nq * 2 + 1], a[mi], b[sp][nq] + 2);
                }
    }

    // ---- epilogue: v = clip(round(0.25*s1*(a1 + a2/128 + a3/16384) + 4*bias))
    float bv[4][2], sv[4][2];
#pragma unroll
    for (int nj = 0; nj < 4; ++nj)
#pragma unroll
        for (int e = 0; e < 2; ++e) {
            int f = fbase + wn + nj * 8 + ((lane & 3) << 1) + e;
            bv[nj][e] = bias[f] * 4.0f;
            sv[nj][e] = g_s1[f] * 0.25f;
        }

#pragma unroll
    for (int mi = 0; mi < 2; ++mi) {
        int m0 = mbase + wm + (mi << 4) + (lane >> 2);
#pragma unroll
        for (int half = 0; half < 2; ++half) {
            int g = m0 + half * 8;
            int n_img = g / ROWS_N;
            int rr = g - n_img * ROWS_N;
            int y = rr / WP;
            int x = rr - y * WP;
            bool valid = (g < MGLOB) && (y < HH) && (x < WW);
            float* ob = valid ? (out + ((size_t)n_img * FNO) * OHW + y * WW + x) : out;
#pragma unroll
            for (int nj = 0; nj < 4; ++nj) {
#pragma unroll
                for (int e = 0; e < 2; ++e) {
                    int f = fbase + wn + nj * 8 + ((lane & 3) << 1) + e;
                    int idx = half * 2 + e;
                    float tot = (float)acc[0][mi][nj][idx]
                              + (float)acc[1][mi][nj][idx] * 0.0078125f
                              + (float)acc[2][mi][nj][idx] * 6.103515625e-05f;
                    float v = rintf(fmaf(sv[nj][e], tot, bv[nj][e]));
                    v = fminf(127.0f, fmaxf(-128.0f, v));
                    if (valid) ob[(size_t)f * OHW] = v;
                }
            }
        }
    }
}

// ---------------- host ----------------
extern "C" void kernel_launch(void* const* d_in, const int* in_sizes, int n_in,
                              void* d_out, int out_size) {
    const float* in_data = (const float*)d_in[0];
    const float* weight  = (const float*)d_in[1];
    const float* bias    = (const float*)d_in[2];
    float* out = (float*)d_out;

    cudaFuncSetAttribute(conv_mma_kernel, cudaFuncAttributeMaxDynamicSharedMemorySize,
                         SMEM_TOTAL);

    {
        const int total = NB * 212 * (CC / 16);
        zero_halo_kernel<<<(total + 255) / 256, 256>>>();
    }
    {
        dim3 grid(16, HH, NB), blk(32, 32);
        quant_kernel<<<grid, blk>>>(in_data);
    }
    s1_kernel<<<FNO, 128>>>(weight);
    {
        dim3 grid(FNO / 32, CC / 32, 9), blk(32, 32);
        wq_kernel<<<grid, blk>>>(weight);
    }
    {
        dim3 grid(FNO / BN, MTILES);   // (8, 183) = 1464 CTAs
        conv_mma_kernel<<<grid, 256, SMEM_TOTAL>>>(bias, out);
    }
}

// round 10
// speedup vs baseline: 4.6506x; 4.6506x over previous
#include <cuda_runtime.h>
#include <cuda_fp16.h>
#include <cstdint>

// ---------------- geometry ----------------
#define NB    8
#define CC    256
#define HH    52
#define WW    52
#define FNO   512
#define HP    54
#define WP    54
#define ROWS_N (HP*WP)          // 2916
#define MGLOB  (NB*ROWS_N)      // 23328
#define OHW    (HH*WW)          // 2704

// ---------------- GEMM tiling ----------------
#define BM 128
#define BN 128
#define BK 32                   // halfs per stage
#define STAGES 4
#define ITERS  72               // 9 taps * (256/32)
#define A_SM   (BM*64)          // 8 KB
#define B_SM   (2*BN*64)        // 16 KB (2 fp16 splits)
#define STG_SM (A_SM + B_SM)    // 24 KB
#define SM_BAR (STAGES*STG_SM)  // barrier block offset (96 KB)
#define SMEM_TOTAL (SM_BAR + 128)
#define MTILES ((MGLOB + BM - 1) / BM)   // 183

// XOR swizzle: 16B chunk k (0..3) within 64B row r -> conflict-free ldmatrix
#define SWZ(r,k) (((r)<<6) + ((((k) ^ (((r)>>1)&3))) << 4))

// ---------------- device scratch ----------------
__device__ __half g_xh[MGLOB * CC];          // padded NHWC quantized fp16
__device__ __half g_w2[2 * 9 * FNO * CC];    // [split][tap][f][c] fp16

// ---------------- asm helpers ----------------
__device__ __forceinline__ uint32_t smem_u32(const void* p) {
    uint32_t a;
    asm("{ .reg .u64 t; cvta.to.shared.u64 t, %1; cvt.u32.u64 %0, t; }" : "=r"(a) : "l"(p));
    return a;
}
__device__ __forceinline__ void cp16(uint32_t s, const void* g) {
    asm volatile("cp.async.cg.shared.global [%0], [%1], 16;" :: "r"(s), "l"(g));
}
// FIX vs R9: .noinc — arrival counts against the preinitialized count instead
// of self-balancing (default form increments pending count -> barrier never flips).
__device__ __forceinline__ void cp_arrive(uint32_t m) {
    asm volatile("cp.async.mbarrier.arrive.noinc.shared.b64 [%0];" :: "r"(m) : "memory");
}
__device__ __forceinline__ void mbar_init(uint32_t m, uint32_t cnt) {
    asm volatile("mbarrier.init.shared.b64 [%0], %1;" :: "r"(m), "r"(cnt) : "memory");
}
__device__ __forceinline__ void mbar_arrive(uint32_t m) {
    asm volatile("mbarrier.arrive.shared.b64 _, [%0];" :: "r"(m) : "memory");
}
__device__ __forceinline__ void mbar_wait(uint32_t m, uint32_t par) {
    asm volatile("{\n\t.reg .pred P;\n\tWL_%=:\n\t"
        "mbarrier.try_wait.parity.shared.b64 P, [%0], %1;\n\t"
        "@P bra.uni WD_%=;\n\tbra.uni WL_%=;\n\tWD_%=:\n\t}"
        :: "r"(m), "r"(par) : "memory");
}
__device__ __forceinline__ void ldsm4(uint32_t& r0, uint32_t& r1, uint32_t& r2, uint32_t& r3,
                                      uint32_t a) {
    asm volatile("ldmatrix.sync.aligned.m8n8.x4.shared.b16 {%0,%1,%2,%3}, [%4];"
                 : "=r"(r0), "=r"(r1), "=r"(r2), "=r"(r3) : "r"(a));
}
__device__ __forceinline__ void mma16816(float* d, const uint32_t* a, const uint32_t* b) {
    asm volatile("mma.sync.aligned.m16n8k16.row.col.f32.f16.f16.f32 "
                 "{%0,%1,%2,%3}, {%4,%5,%6,%7}, {%8,%9}, {%0,%1,%2,%3};"
                 : "+f"(d[0]), "+f"(d[1]), "+f"(d[2]), "+f"(d[3])
                 : "r"(a[0]), "r"(a[1]), "r"(a[2]), "r"(a[3]), "r"(b[0]), "r"(b[1]));
}

// ---------------- kernel 0: zero only the padding halo ----------------
__global__ void zero_halo_kernel() {
    int idx = blockIdx.x * blockDim.x + threadIdx.x;
    const int total = NB * 212 * (CC / 8);
    if (idx >= total) return;
    int v = idx & 31;
    int h = (idx >> 5) % 212;
    int n = idx / (212 * 32);
    int y, x;
    if (h < 54)       { y = 0;  x = h; }
    else if (h < 108) { y = 53; x = h - 54; }
    else { int r = h - 108; y = 1 + (r >> 1); x = (r & 1) ? 53 : 0; }
    uint4 z = {0, 0, 0, 0};
    reinterpret_cast<uint4*>(g_xh + ((size_t)n * ROWS_N + y * WP + x) * CC)[v] = z;
}

// ---------------- kernel 1: quantize + NCHW->NHWC transpose (interior) -------
__global__ void quant_kernel(const float* __restrict__ in) {
    __shared__ float tile[32][33];
    const int n = blockIdx.z, y = blockIdx.y;
    const int xt = blockIdx.x & 1, ct = blockIdx.x >> 1;
    const int tx = threadIdx.x, ty = threadIdx.y;

    int x = xt * 32 + tx, c = ct * 32 + ty;
    if (x < WW) {
        float v = in[((n * CC + c) * HH + y) * WW + x];
        v = rintf(v * 20.0f);
        tile[ty][tx] = fminf(127.0f, fmaxf(-128.0f, v));
    }
    __syncthreads();
    int x2 = xt * 32 + ty, c2 = ct * 32 + tx;
    if (x2 < WW)
        g_xh[((size_t)n * ROWS_N + (y + 1) * WP + (x2 + 1)) * CC + c2] =
            __float2half_rn(tile[tx][ty]);
}

// ---------------- kernel 2: weight 2-way fp16 split + transpose --------------
__global__ void wprep_kernel(const float* __restrict__ w) {
    __shared__ __half t0[32][33], t1[32][33];
    const int tap = blockIdx.z;
    const int tx = threadIdx.x, ty = threadIdx.y;
    const int c = blockIdx.y * 32 + ty;
    const int f = blockIdx.x * 32 + tx;

    float v = w[((size_t)c * 9 + tap) * FNO + f];
    __half h0 = __float2half_rn(v);
    float r1 = v - __half2float(h0);
    __half h1 = __float2half_rn(r1);
    t0[ty][tx] = h0; t1[ty][tx] = h1;
    __syncthreads();

    const int c2 = blockIdx.y * 32 + tx;
    const int f2 = blockIdx.x * 32 + ty;
    size_t base = ((size_t)tap * FNO + f2) * CC + c2;
    const size_t sstr = (size_t)9 * FNO * CC;
    g_w2[base]        = t0[tx][ty];
    g_w2[base + sstr] = t1[tx][ty];
}

// ---------------- kernel 3: mma.sync implicit-GEMM conv ----------------------
// 256 threads (8 warps, 2m x 4n of 64x32 warp tiles), 2 CTAs/SM.
// mbarrier-decoupled 4-stage pipeline: NO __syncthreads in mainloop.
__global__ __launch_bounds__(256, 2)
void conv_mma_kernel(const float* __restrict__ bias, float* __restrict__ out) {
    extern __shared__ char smem[];
    const uint32_t sb = smem_u32(smem);
    const int tid  = threadIdx.x;
    const int lane = tid & 31, wid = tid >> 5;
    const int fbase = blockIdx.x * BN;
    const int mbase = blockIdx.y * BM;
    const int wm = (wid & 1) << 6;   // warp m-offset (0/64)
    const int wn = (wid >> 1) << 5;  // warp n-offset (0/32/64/96)

    // barriers: full[s] at SM_BAR + s*8 (count 256), empty[s] at +32 (count 8)
    const uint32_t fullb  = sb + SM_BAR;
    const uint32_t emptyb = sb + SM_BAR + 32;
    if (tid == 0) {
#pragma unroll
        for (int s = 0; s < STAGES; ++s) {
            mbar_init(fullb + s * 8, 256);
            mbar_init(emptyb + s * 8, 8);
        }
    }
    __syncthreads();

    float acc[4][4][4];
#pragma unroll
    for (int a = 0; a < 4; ++a)
#pragma unroll
        for (int b = 0; b < 4; ++b)
#pragma unroll
            for (int c = 0; c < 4; ++c) acc[a][b][c] = 0.0f;

    auto issue = [&](int it) {
        const int tap = it >> 3;
        const int c0  = (it & 7) << 5;
        const int taprow = (tap / 3) * WP + (tap % 3);
        const uint32_t sA = sb + (uint32_t)(it & (STAGES - 1)) * STG_SM;
        const uint32_t sB = sA + A_SM;
        // A: 512 chunks (128 rows x 4), 2 per thread
#pragma unroll
        for (int j = 0; j < 2; ++j) {
            int cid = tid + (j << 8);
            int r = cid >> 2, k = cid & 3;
            int grow = mbase + r + taprow;
            if (grow > MGLOB - 1) grow = MGLOB - 1;
            cp16(sA + SWZ(r, k), g_xh + (size_t)grow * CC + c0 + (k << 3));
        }
        // B: 1024 chunks (2 splits x 128 rows x 4), 4 per thread
#pragma unroll
        for (int j = 0; j < 4; ++j) {
            int cid = tid + (j << 8);
            int sp = cid >> 9, rem = cid & 511;
            int fr = rem >> 2, k = rem & 3;
            cp16(sB + sp * 8192 + SWZ(fr, k),
                 g_w2 + ((size_t)(sp * 9 + tap) * FNO + fbase + fr) * CC + c0 + (k << 3));
        }
        cp_arrive(fullb + (uint32_t)(it & (STAGES - 1)) * 8);
    };

    // prologue: stages 0..2 (buffers free, no empty wait)
    issue(0); issue(1); issue(2);

#pragma unroll 1
    for (int i = 0; i < ITERS; ++i) {
        // ---- produce stage i+3 ----
        int nx = i + 3;
        if (nx < ITERS) {
            if (nx >= STAGES)
                mbar_wait(emptyb + (uint32_t)(nx & (STAGES - 1)) * 8,
                          ((nx >> 2) - 1) & 1);
            issue(nx);
        }

        // ---- consume stage i ----
        const uint32_t sA = sb + (uint32_t)(i & (STAGES - 1)) * STG_SM;
        const uint32_t sB = sA + A_SM;
        mbar_wait(fullb + (uint32_t)(i & (STAGES - 1)) * 8, (i >> 2) & 1);

#pragma unroll
        for (int k16 = 0; k16 < 2; ++k16) {
            uint32_t a[4][4];
#pragma unroll
            for (int mi = 0; mi < 4; ++mi) {
                int r  = wm + (mi << 4) + (lane & 15);
                int kc = (k16 << 1) + (lane >> 4);
                ldsm4(a[mi][0], a[mi][1], a[mi][2], a[mi][3], sA + SWZ(r, kc));
            }
#pragma unroll
            for (int sp = 0; sp < 2; ++sp) {
#pragma unroll
                for (int nj = 0; nj < 2; ++nj) {
                    int r  = wn + (nj << 4) + ((lane >> 4) << 3) + (lane & 7);
                    int kc = (k16 << 1) + ((lane >> 3) & 1);
                    uint32_t b[4];
                    ldsm4(b[0], b[1], b[2], b[3], sB + sp * 8192 + SWZ(r, kc));
#pragma unroll
                    for (int mi = 0; mi < 4; ++mi) {
                        mma16816(acc[mi][nj * 2],     a[mi], b);
                        mma16816(acc[mi][nj * 2 + 1], a[mi], b + 2);
                    }
                }
            }
        }
        // release stage i (warp-level: lane 0 arrives; count = 8 warps)
        if (lane == 0)
            mbar_arrive(emptyb + (uint32_t)(i & (STAGES - 1)) * 8);
    }

    // ---------------- epilogue: clip(round(0.25*acc + 4*bias)) -> NCHW -------
    float bv[4][2];
#pragma unroll
    for (int nj2 = 0; nj2 < 4; ++nj2)
#pragma unroll
        for (int e = 0; e < 2; ++e)
            bv[nj2][e] = bias[fbase + wn + nj2 * 8 + ((lane & 3) << 1) + e] * 4.0f;

#pragma unroll
    for (int mi = 0; mi < 4; ++mi) {
        int m0 = mbase + wm + (mi << 4) + (lane >> 2);
#pragma unroll
        for (int half = 0; half < 2; ++half) {
            int g = m0 + half * 8;
            int n_img = g / ROWS_N;
            int rr = g - n_img * ROWS_N;
            int y = rr / WP;
            int x = rr - y * WP;
            bool valid = (g < MGLOB) && (y < HH) && (x < WW);
            float* ob = valid ? (out + ((size_t)n_img * FNO) * OHW + y * WW + x) : out;
#pragma unroll
            for (int nj2 = 0; nj2 < 4; ++nj2) {
#pragma unroll
                for (int e = 0; e < 2; ++e) {
                    int f = fbase + wn + nj2 * 8 + ((lane & 3) << 1) + e;
                    float v = acc[mi][nj2][half * 2 + e] * 0.25f + bv[nj2][e];
                    v = rintf(v);
                    v = fminf(127.0f, fmaxf(-128.0f, v));
                    if (valid) ob[(size_t)f * OHW] = v;
                }
            }
        }
    }
}

// ---------------- host ----------------
extern "C" void kernel_launch(void* const* d_in, const int* in_sizes, int n_in,
                              void* d_out, int out_size) {
    const float* in_data = (const float*)d_in[0];
    const float* weight  = (const float*)d_in[1];
    const float* bias    = (const float*)d_in[2];
    float* out = (float*)d_out;

    cudaFuncSetAttribute(conv_mma_kernel, cudaFuncAttributeMaxDynamicSharedMemorySize,
                         SMEM_TOTAL);

    {
        const int total = NB * 212 * (CC / 8);
        zero_halo_kernel<<<(total + 255) / 256, 256>>>();
    }
    {
        dim3 grid(16, HH, NB), blk(32, 32);
        quant_kernel<<<grid, blk>>>(in_data);
    }
    {
        dim3 grid(FNO / 32, CC / 32, 9), blk(32, 32);
        wprep_kernel<<<grid, blk>>>(weight);
    }
    {
        dim3 grid(FNO / BN, MTILES);   // (4, 183)
        conv_mma_kernel<<<grid, 256, SMEM_TOTAL>>>(bias, out);
    }
}

// round 11
// speedup vs baseline: 5.2407x; 1.1269x over previous
#include <cuda_runtime.h>
#include <cuda_fp16.h>
#include <cstdint>

// ---------------- geometry ----------------
#define NB    8
#define CC    256
#define HH    52
#define WW    52
#define FNO   512
#define HP    54
#define WP    54
#define ROWS_N (HP*WP)          // 2916
#define MGLOB  (NB*ROWS_N)      // 23328
#define OHW    (HH*WW)          // 2704

// ---------------- GEMM tiling ----------------
#define BM 128
#define BN 128
#define BK 32                   // halfs per stage
#define STAGES 4
#define ITERS  72               // 9 taps * (256/32)
#define A_SM   (BM*64)          // 8 KB
#define B_SM   (2*BN*64)        // 16 KB (2 fp16 splits)
#define STG_SM (A_SM + B_SM)    // 24 KB
#define SM_BAR (STAGES*STG_SM)  // barrier block offset (96 KB)
#define SMEM_TOTAL (SM_BAR + 128)
#define MTILES ((MGLOB + BM - 1) / BM)   // 183

// prep kernel block ranges
#define QBLKS (16*HH*NB)        // 6656 quant blocks
#define WBLKS ((FNO/32)*(CC/32)*9)  // 1152 wprep blocks
#define HBLKS 212               // halo blocks (212*256 = NB*212*32 threads)

// XOR swizzle: 16B chunk k (0..3) within 64B row r -> conflict-free ldmatrix
#define SWZ(r,k) (((r)<<6) + ((((k) ^ (((r)>>1)&3))) << 4))

// ---------------- device scratch ----------------
__device__ __half g_xh[MGLOB * CC];          // padded NHWC quantized fp16
__device__ __half g_w2[2 * 9 * FNO * CC];    // [split][tap][f][c] fp16

// ---------------- asm helpers ----------------
__device__ __forceinline__ uint32_t smem_u32(const void* p) {
    uint32_t a;
    asm("{ .reg .u64 t; cvta.to.shared.u64 t, %1; cvt.u32.u64 %0, t; }" : "=r"(a) : "l"(p));
    return a;
}
__device__ __forceinline__ void cp16(uint32_t s, const void* g) {
    asm volatile("cp.async.cg.shared.global [%0], [%1], 16;" :: "r"(s), "l"(g));
}
__device__ __forceinline__ void cp_arrive(uint32_t m) {
    asm volatile("cp.async.mbarrier.arrive.noinc.shared.b64 [%0];" :: "r"(m) : "memory");
}
__device__ __forceinline__ void mbar_init(uint32_t m, uint32_t cnt) {
    asm volatile("mbarrier.init.shared.b64 [%0], %1;" :: "r"(m), "r"(cnt) : "memory");
}
__device__ __forceinline__ void mbar_arrive(uint32_t m) {
    asm volatile("mbarrier.arrive.shared.b64 _, [%0];" :: "r"(m) : "memory");
}
__device__ __forceinline__ void mbar_wait(uint32_t m, uint32_t par) {
    asm volatile("{\n\t.reg .pred P;\n\tWL_%=:\n\t"
        "mbarrier.try_wait.parity.shared.b64 P, [%0], %1;\n\t"
        "@P bra.uni WD_%=;\n\tbra.uni WL_%=;\n\tWD_%=:\n\t}"
        :: "r"(m), "r"(par) : "memory");
}
__device__ __forceinline__ void ldsm4(uint32_t& r0, uint32_t& r1, uint32_t& r2, uint32_t& r3,
                                      uint32_t a) {
    asm volatile("ldmatrix.sync.aligned.m8n8.x4.shared.b16 {%0,%1,%2,%3}, [%4];"
                 : "=r"(r0), "=r"(r1), "=r"(r2), "=r"(r3) : "r"(a));
}
__device__ __forceinline__ void mma16816(float* d, const uint32_t* a, const uint32_t* b) {
    asm volatile("mma.sync.aligned.m16n8k16.row.col.f32.f16.f16.f32 "
                 "{%0,%1,%2,%3}, {%4,%5,%6,%7}, {%8,%9}, {%0,%1,%2,%3};"
                 : "+f"(d[0]), "+f"(d[1]), "+f"(d[2]), "+f"(d[3])
                 : "r"(a[0]), "r"(a[1]), "r"(a[2]), "r"(a[3]), "r"(b[0]), "r"(b[1]));
}

// ---------------- fused prep kernel (quant + wprep + halo in one launch) -----
// 256 threads per block. Block ranges:
//   [0, QBLKS)              : quantize + NCHW->NHWC transpose (interior)
//   [QBLKS, QBLKS+WBLKS)    : weight 2-way fp16 split + transpose
//   [QBLKS+WBLKS, +HBLKS)   : zero padding halo
__global__ __launch_bounds__(256)
void prep_kernel(const float* __restrict__ in, const float* __restrict__ w) {
    const int bid = blockIdx.x;
    const int tid = threadIdx.x;
    const int tx = tid & 31, ty8 = tid >> 5;   // 32 x 8

    if (bid < QBLKS) {
        __shared__ float tile[32][33];
        int xc = bid & 15;
        int y  = (bid >> 4) % HH;
        int n  = bid / (16 * HH);
        int xt = xc & 1, ct = xc >> 1;
        int x = xt * 32 + tx;
#pragma unroll
        for (int j = 0; j < 4; ++j) {
            int c = ct * 32 + ty8 + j * 8;
            if (x < WW) {
                float v = in[((n * CC + c) * HH + y) * WW + x];
                v = rintf(v * 20.0f);
                tile[ty8 + j * 8][tx] = fminf(127.0f, fmaxf(-128.0f, v));
            }
        }
        __syncthreads();
#pragma unroll
        for (int j = 0; j < 4; ++j) {
            int x2 = xt * 32 + ty8 + j * 8;
            int c2 = ct * 32 + tx;
            if (x2 < WW)
                g_xh[((size_t)n * ROWS_N + (y + 1) * WP + (x2 + 1)) * CC + c2] =
                    __float2half_rn(tile[tx][ty8 + j * 8]);
        }
    } else if (bid < QBLKS + WBLKS) {
        __shared__ __half t0[32][33], t1[32][33];
        int b = bid - QBLKS;
        int fb = b & 15;                 // 16 f-tiles
        int cb = (b >> 4) & 7;           // 8 c-tiles
        int tap = b >> 7;                // 9 taps
        const int f = fb * 32 + tx;
#pragma unroll
        for (int j = 0; j < 4; ++j) {
            int c = cb * 32 + ty8 + j * 8;
            float v = w[((size_t)c * 9 + tap) * FNO + f];
            __half h0 = __float2half_rn(v);
            float r1 = v - __half2float(h0);
            __half h1 = __float2half_rn(r1);
            t0[ty8 + j * 8][tx] = h0;
            t1[ty8 + j * 8][tx] = h1;
        }
        __syncthreads();
        const size_t sstr = (size_t)9 * FNO * CC;
#pragma unroll
        for (int j = 0; j < 4; ++j) {
            int c2 = cb * 32 + tx;
            int f2 = fb * 32 + ty8 + j * 8;
            size_t base = ((size_t)tap * FNO + f2) * CC + c2;
            g_w2[base]        = t0[tx][ty8 + j * 8];
            g_w2[base + sstr] = t1[tx][ty8 + j * 8];
        }
    } else {
        int idx = (bid - QBLKS - WBLKS) * 256 + tid;
        const int total = NB * 212 * (CC / 8);
        if (idx >= total) return;
        int v = idx & 31;
        int h = (idx >> 5) % 212;
        int n = idx / (212 * 32);
        int y, x;
        if (h < 54)       { y = 0;  x = h; }
        else if (h < 108) { y = 53; x = h - 54; }
        else { int r = h - 108; y = 1 + (r >> 1); x = (r & 1) ? 53 : 0; }
        uint4 z = {0, 0, 0, 0};
        reinterpret_cast<uint4*>(g_xh + ((size_t)n * ROWS_N + y * WP + x) * CC)[v] = z;
    }
}

// ---------------- conv kernel: mma.sync implicit GEMM ------------------------
// 256 threads (8 warps, 2m x 4n of 64x32 warp tiles), 2 CTAs/SM.
// mbarrier-decoupled 4-stage pipeline; early stage release after last ldsm.
__global__ __launch_bounds__(256, 2)
void conv_mma_kernel(const float* __restrict__ bias, float* __restrict__ out) {
    extern __shared__ char smem[];
    const uint32_t sb = smem_u32(smem);
    const int tid  = threadIdx.x;
    const int lane = tid & 31, wid = tid >> 5;
    const int fbase = blockIdx.x * BN;
    const int mbase = blockIdx.y * BM;
    const int wm = (wid & 1) << 6;   // warp m-offset (0/64)
    const int wn = (wid >> 1) << 5;  // warp n-offset (0/32/64/96)

    const uint32_t fullb  = sb + SM_BAR;        // count 256 (cp.async noinc)
    const uint32_t emptyb = sb + SM_BAR + 32;   // count 8 (one arrive per warp)
    if (tid == 0) {
#pragma unroll
        for (int s = 0; s < STAGES; ++s) {
            mbar_init(fullb + s * 8, 256);
            mbar_init(emptyb + s * 8, 8);
        }
    }
    __syncthreads();

    float acc[4][4][4];
#pragma unroll
    for (int a = 0; a < 4; ++a)
#pragma unroll
        for (int b = 0; b < 4; ++b)
#pragma unroll
            for (int c = 0; c < 4; ++c) acc[a][b][c] = 0.0f;

    auto issue = [&](int it) {
        const int tap = it >> 3;
        const int c0  = (it & 7) << 5;
        const int taprow = (tap / 3) * WP + (tap % 3);
        const uint32_t sA = sb + (uint32_t)(it & (STAGES - 1)) * STG_SM;
        const uint32_t sB = sA + A_SM;
#pragma unroll
        for (int j = 0; j < 2; ++j) {
            int cid = tid + (j << 8);
            int r = cid >> 2, k = cid & 3;
            int grow = mbase + r + taprow;
            if (grow > MGLOB - 1) grow = MGLOB - 1;
            cp16(sA + SWZ(r, k), g_xh + (size_t)grow * CC + c0 + (k << 3));
        }
#pragma unroll
        for (int j = 0; j < 4; ++j) {
            int cid = tid + (j << 8);
            int sp = cid >> 9, rem = cid & 511;
            int fr = rem >> 2, k = rem & 3;
            cp16(sB + sp * 8192 + SWZ(fr, k),
                 g_w2 + ((size_t)(sp * 9 + tap) * FNO + fbase + fr) * CC + c0 + (k << 3));
        }
        cp_arrive(fullb + (uint32_t)(it & (STAGES - 1)) * 8);
    };

    issue(0); issue(1); issue(2);

#pragma unroll 1
    for (int i = 0; i < ITERS; ++i) {
        const uint32_t sA = sb + (uint32_t)(i & (STAGES - 1)) * STG_SM;
        const uint32_t sB = sA + A_SM;
        mbar_wait(fullb + (uint32_t)(i & (STAGES - 1)) * 8, (i >> 2) & 1);

        // ---- k16 = 0: loads ----
        uint32_t a0[4][4], b0[2][2][4];
#pragma unroll
        for (int mi = 0; mi < 4; ++mi) {
            int r = wm + (mi << 4) + (lane & 15);
            ldsm4(a0[mi][0], a0[mi][1], a0[mi][2], a0[mi][3],
                  sA + SWZ(r, (lane >> 4)));
        }
#pragma unroll
        for (int sp = 0; sp < 2; ++sp)
#pragma unroll
            for (int nj = 0; nj < 2; ++nj) {
                int r = wn + (nj << 4) + ((lane >> 4) << 3) + (lane & 7);
                ldsm4(b0[sp][nj][0], b0[sp][nj][1], b0[sp][nj][2], b0[sp][nj][3],
                      sB + sp * 8192 + SWZ(r, ((lane >> 3) & 1)));
            }

        // ---- produce stage i+3 in the ldsm latency shadow ----
        int nx = i + 3;
        if (nx < ITERS) {
            if (nx >= STAGES)
                mbar_wait(emptyb + (uint32_t)(nx & (STAGES - 1)) * 8,
                          ((nx >> 2) - 1) & 1);
            issue(nx);
        }

        // ---- k16 = 0: MMAs ----
#pragma unroll
        for (int sp = 0; sp < 2; ++sp)
#pragma unroll
            for (int nj = 0; nj < 2; ++nj)
#pragma unroll
                for (int mi = 0; mi < 4; ++mi) {
                    mma16816(acc[mi][nj * 2],     a0[mi], b0[sp][nj]);
                    mma16816(acc[mi][nj * 2 + 1], a0[mi], b0[sp][nj] + 2);
                }

        // ---- k16 = 1: loads, then EARLY release, then MMAs ----
        uint32_t a1[4][4], b1[2][2][4];
#pragma unroll
        for (int mi = 0; mi < 4; ++mi) {
            int r = wm + (mi << 4) + (lane & 15);
            ldsm4(a1[mi][0], a1[mi][1], a1[mi][2], a1[mi][3],
                  sA + SWZ(r, 2 + (lane >> 4)));
        }
#pragma unroll
        for (int sp = 0; sp < 2; ++sp)
#pragma unroll
            for (int nj = 0; nj < 2; ++nj) {
                int r = wn + (nj << 4) + ((lane >> 4) << 3) + (lane & 7);
                ldsm4(b1[sp][nj][0], b1[sp][nj][1], b1[sp][nj][2], b1[sp][nj][3],
                      sB + sp * 8192 + SWZ(r, 2 + ((lane >> 3) & 1)));
            }
        if (lane == 0)
            mbar_arrive(emptyb + (uint32_t)(i & (STAGES - 1)) * 8);
#pragma unroll
        for (int sp = 0; sp < 2; ++sp)
#pragma unroll
            for (int nj = 0; nj < 2; ++nj)
#pragma unroll
                for (int mi = 0; mi < 4; ++mi) {
                    mma16816(acc[mi][nj * 2],     a1[mi], b1[sp][nj]);
                    mma16816(acc[mi][nj * 2 + 1], a1[mi], b1[sp][nj] + 2);
                }
    }

    // ---------------- epilogue: clip(round(0.25*acc + 4*bias)) -> NCHW -------
    float bv[4][2];
#pragma unroll
    for (int nj2 = 0; nj2 < 4; ++nj2)
#pragma unroll
        for (int e = 0; e < 2; ++e)
            bv[nj2][e] = bias[fbase + wn + nj2 * 8 + ((lane & 3) << 1) + e] * 4.0f;

#pragma unroll
    for (int mi = 0; mi < 4; ++mi) {
        int m0 = mbase + wm + (mi << 4) + (lane >> 2);
#pragma unroll
        for (int half = 0; half < 2; ++half) {
            int g = m0 + half * 8;
            int n_img = g / ROWS_N;
            int rr = g - n_img * ROWS_N;
            int y = rr / WP;
            int x = rr - y * WP;
            bool valid = (g < MGLOB) && (y < HH) && (x < WW);
            float* ob = valid ? (out + ((size_t)n_img * FNO) * OHW + y * WW + x) : out;
#pragma unroll
            for (int nj2 = 0; nj2 < 4; ++nj2) {
#pragma unroll
                for (int e = 0; e < 2; ++e) {
                    int f = fbase + wn + nj2 * 8 + ((lane & 3) << 1) + e;
                    float v = acc[mi][nj2][half * 2 + e] * 0.25f + bv[nj2][e];
                    v = rintf(v);
                    v = fminf(127.0f, fmaxf(-128.0f, v));
                    if (valid) ob[(size_t)f * OHW] = v;
                }
            }
        }
    }
}

// ---------------- host ----------------
extern "C" void kernel_launch(void* const* d_in, const int* in_sizes, int n_in,
                              void* d_out, int out_size) {
    const float* in_data = (const float*)d_in[0];
    const float* weight  = (const float*)d_in[1];
    const float* bias    = (const float*)d_in[2];
    float* out = (float*)d_out;

    cudaFuncSetAttribute(conv_mma_kernel, cudaFuncAttributeMaxDynamicSharedMemorySize,
                         SMEM_TOTAL);

    prep_kernel<<<QBLKS + WBLKS + HBLKS, 256>>>(in_data, weight);
    {
        dim3 grid(FNO / BN, MTILES);   // (4, 183)
        conv_mma_kernel<<<grid, 256, SMEM_TOTAL>>>(bias, out);
    }
}